// round 10
// baseline (speedup 1.0000x reference)
#include <cuda_runtime.h>
#include <cstdint>

#define D        1032            // floats per weight row
#define CHUNK_F  344             // floats per column chunk (3 * 344 = 1032)
#define NCHUNK   3
#define MAX_ACTIVE 32
#define BATCH    4096
#define THREADS  192             // 6 warps; each thread loads one float2 per gather
#define TOTAL_F  46497792        // 45056 * 1032

__global__ __launch_bounds__(THREADS)
void ft_aligned_kernel(const int*   __restrict__ idx0,
                       const float* __restrict__ val0,
                       const int*   __restrict__ idx1,
                       const float* __restrict__ val1,
                       const float* __restrict__ W,
                       const float* __restrict__ bias,
                       float*       __restrict__ out)
{
    const int r     = blockIdx.x;        // 0..8191 : both feature sets
    const int chunk = blockIdx.y;        // 0..2    : slow dim -> L2 phases
    const int tid   = threadIdx.x;

    const int*   idx;
    const float* val;
    int row;
    if (r < BATCH) { idx = idx0; val = val0; row = r; }
    else           { idx = idx1; val = val1; row = r - BATCH; }

    // (A, v) pairs sorted by alignment-shift class, packed for single LDS.64
    __shared__ float2 sAV[MAX_ACTIVE];   // .x = __int_as_float(A), .y = v
    __shared__ int    sBnd[5];           // class boundaries in sorted order
    __shared__ float  cs[CHUNK_F];       // column combine scratch

    if (tid < 32) {                      // exactly warp 0
        const int f = idx[row * 32 + tid];
        const int F = f * D + chunk * CHUNK_F;   // chunk start (float offset)
        const int s = F & 31;                    // shift: 0, 8, 16, or 24
        const int j = s >> 3;                    // class 0..3
        const unsigned b0 = __ballot_sync(0xffffffffu, j == 0);
        const unsigned b1 = __ballot_sync(0xffffffffu, j == 1);
        const unsigned b2 = __ballot_sync(0xffffffffu, j == 2);
        const unsigned b3 = __ballot_sync(0xffffffffu, j == 3);
        const unsigned lt = (1u << tid) - 1u;
        int st; unsigned bj;
        if      (j == 0) { st = 0;                                         bj = b0; }
        else if (j == 1) { st = __popc(b0);                                bj = b1; }
        else if (j == 2) { st = __popc(b0) + __popc(b1);                   bj = b2; }
        else             { st = __popc(b0) + __popc(b1) + __popc(b2);      bj = b3; }
        const int pos = st + __popc(bj & lt);
        sAV[pos] = make_float2(__int_as_float(F - s), val[row * 32 + tid]);
        if (tid == 0) {
            sBnd[0] = 0;
            sBnd[1] = __popc(b0);
            sBnd[2] = __popc(b0) + __popc(b1);
            sBnd[3] = __popc(b0) + __popc(b1) + __popc(b2);
            sBnd[4] = 32;
        }
    }
    __syncthreads();

    const int t2 = 2 * tid;              // this thread's aligned-window slot
    float2 a0 = make_float2(0.f, 0.f);   // class-j acc: columns (2t-8j, 2t+1-8j)
    float2 a1 = a0, a2 = a0, a3 = a0;

    // Four class sub-loops; every warp LDG.64 covers an exact 256B-aligned span.
    // Clamp handles the array-tail edge: it only corrupts columns >= 344 (unread).
    {
        const int e = sBnd[1];
        for (int k = 0; k < e; ++k) {
            const float2 av = sAV[k];
            const int a = min(__float_as_int(av.x) + t2, TOTAL_F - 2);
            const float2 w = *(const float2*)(W + a);
            a0.x = fmaf(w.x, av.y, a0.x);
            a0.y = fmaf(w.y, av.y, a0.y);
        }
    }
    {
        const int b = sBnd[1], e = sBnd[2];
        for (int k = b; k < e; ++k) {
            const float2 av = sAV[k];
            const int a = min(__float_as_int(av.x) + t2, TOTAL_F - 2);
            const float2 w = *(const float2*)(W + a);
            a1.x = fmaf(w.x, av.y, a1.x);
            a1.y = fmaf(w.y, av.y, a1.y);
        }
    }
    {
        const int b = sBnd[2], e = sBnd[3];
        for (int k = b; k < e; ++k) {
            const float2 av = sAV[k];
            const int a = min(__float_as_int(av.x) + t2, TOTAL_F - 2);
            const float2 w = *(const float2*)(W + a);
            a2.x = fmaf(w.x, av.y, a2.x);
            a2.y = fmaf(w.y, av.y, a2.y);
        }
    }
    {
        const int b = sBnd[3];
        for (int k = b; k < 32; ++k) {
            const float2 av = sAV[k];
            const int a = min(__float_as_int(av.x) + t2, TOTAL_F - 2);
            const float2 w = *(const float2*)(W + a);
            a3.x = fmaf(w.x, av.y, a3.x);
            a3.y = fmaf(w.y, av.y, a3.y);
        }
    }

    // Combine shift classes in SMEM. Pass 0 initializes (covers all c in [0,344)),
    // passes 1..3 accumulate at distinct addresses per pass -> race-free with syncs.
    if (t2     < CHUNK_F) cs[t2]     = a0.x;
    if (t2 + 1 < CHUNK_F) cs[t2 + 1] = a0.y;
    __syncthreads();
    { int c = t2 - 8;  if (c >= 0 && c < CHUNK_F) cs[c] += a1.x;
      c++;             if (c >= 0 && c < CHUNK_F) cs[c] += a1.y; }
    __syncthreads();
    { int c = t2 - 16; if (c >= 0 && c < CHUNK_F) cs[c] += a2.x;
      c++;             if (c >= 0 && c < CHUNK_F) cs[c] += a2.y; }
    __syncthreads();
    { int c = t2 - 24; if (c >= 0 && c < CHUNK_F) cs[c] += a3.x;
      c++;             if (c >= 0 && c < CHUNK_F) cs[c] += a3.y; }
    __syncthreads();

    // Epilogue: add bias, streaming store (written once, never re-read).
    const int   base = chunk * CHUNK_F;
    float* __restrict__ orow = out + (size_t)r * D + base;
    {
        const int c = tid;                       // 0..191 < 344
        __stcs(orow + c, cs[c] + bias[base + c]);
    }
    {
        const int c = tid + THREADS;             // 192..383
        if (c < CHUNK_F)
            __stcs(orow + c, cs[c] + bias[base + c]);
    }
}

extern "C" void kernel_launch(void* const* d_in, const int* in_sizes, int n_in,
                              void* d_out, int out_size)
{
    // metadata order:
    //   0: feature_indices_0  int32  [4096, 32]
    //   1: feature_values_0   f32    [4096, 32]
    //   2: feature_indices_1  int32  [4096, 32]
    //   3: feature_values_1   f32    [4096, 32]
    //   4: merged_weight      f32    [45056, 1032]
    //   5: bias               f32    [1032]
    const int*   idx0 = (const int*)  d_in[0];
    const float* val0 = (const float*)d_in[1];
    const int*   idx1 = (const int*)  d_in[2];
    const float* val1 = (const float*)d_in[3];
    const float* W    = (const float*)d_in[4];
    const float* bias = (const float*)d_in[5];

    float* out = (float*)d_out;      // [8192, 1032] : out0 then out1

    dim3 grid(2 * BATCH, NCHUNK);
    ft_aligned_kernel<<<grid, THREADS>>>(idx0, val0, idx1, val1, W, bias, out);
}

// round 11
// speedup vs baseline: 1.6062x; 1.6062x over previous
#include <cuda_runtime.h>

#define NUM_OUTPUTS 1032
#define D4 258              // 1032 floats = 258 float4 per weight row
#define CHUNK 86            // float4 per column chunk (3 chunks: 86*3 = 258)
#define NCHUNK 3
#define MAX_ACTIVE 32
#define BATCH 4096
#define THREADS 96          // 3 warps; lanes 0..85 active

__global__ __launch_bounds__(THREADS)
void ft_pipe_kernel(const int*    __restrict__ idx0,
                    const float*  __restrict__ val0,
                    const int*    __restrict__ idx1,
                    const float*  __restrict__ val1,
                    const float4* __restrict__ W4,
                    const float4* __restrict__ bias4,
                    float4*       __restrict__ out4)
{
    const int r     = blockIdx.x;          // 0..8191 : both feature sets fused
    const int chunk = blockIdx.y;          // 0..2    : slow dim -> L2 phases
    const int tid   = threadIdx.x;

    const int*   idx;
    const float* val;
    int row;
    if (r < BATCH) { idx = idx0; val = val0; row = r; }
    else           { idx = idx1; val = val1; row = r - BATCH; }

    __shared__ int   sOff[MAX_ACTIVE];     // row offsets in float4 units (fits int)
    __shared__ float sVal[MAX_ACTIVE];
    if (tid < MAX_ACTIVE) {
        sOff[tid] = idx[row * MAX_ACTIVE + tid] * D4;
        sVal[tid] = val[row * MAX_ACTIVE + tid];
    }
    __syncthreads();

    if (tid >= CHUNK) return;              // no barriers below

    const int c = chunk * CHUNK + tid;     // float4 column index, 0..257
    const float4* __restrict__ Wc = W4 + c;

    float4 a = bias4[c];

    // Depth-2 loop-carried software pipeline: the prefetched load feeds the
    // NEXT iteration, so ptxas cannot sink it to its use -> guaranteed 2-3
    // loads in flight per thread while staying near the 32-reg budget.
    float4 w0 = __ldg(Wc + sOff[0]);
    float4 w1 = __ldg(Wc + sOff[1]);
    float  v0 = sVal[0];
    float  v1 = sVal[1];

    #pragma unroll 2
    for (int k = 0; k < MAX_ACTIVE - 2; ++k) {
        const int    on = sOff[k + 2];
        const float  vn = sVal[k + 2];
        const float4 wn = __ldg(Wc + on);   // issued before w0 is consumed
        a.x = fmaf(w0.x, v0, a.x);
        a.y = fmaf(w0.y, v0, a.y);
        a.z = fmaf(w0.z, v0, a.z);
        a.w = fmaf(w0.w, v0, a.w);
        w0 = w1; v0 = v1;
        w1 = wn; v1 = vn;
    }
    // Drain the pipeline (k = 30, 31).
    a.x = fmaf(w0.x, v0, a.x);
    a.y = fmaf(w0.y, v0, a.y);
    a.z = fmaf(w0.z, v0, a.z);
    a.w = fmaf(w0.w, v0, a.w);
    a.x = fmaf(w1.x, v1, a.x);
    a.y = fmaf(w1.y, v1, a.y);
    a.z = fmaf(w1.z, v1, a.z);
    a.w = fmaf(w1.w, v1, a.w);

    // Streaming store: written once, never re-read.
    __stcs(out4 + (size_t)r * D4 + c, a);
}

extern "C" void kernel_launch(void* const* d_in, const int* in_sizes, int n_in,
                              void* d_out, int out_size)
{
    // metadata order:
    //   0: feature_indices_0  int32  [4096, 32]
    //   1: feature_values_0   f32    [4096, 32]
    //   2: feature_indices_1  int32  [4096, 32]
    //   3: feature_values_1   f32    [4096, 32]
    //   4: merged_weight      f32    [45056, 1032]
    //   5: bias               f32    [1032]
    const int*    idx0 = (const int*)   d_in[0];
    const float*  val0 = (const float*) d_in[1];
    const int*    idx1 = (const int*)   d_in[2];
    const float*  val1 = (const float*) d_in[3];
    const float4* W4   = (const float4*)d_in[4];
    const float4* b4   = (const float4*)d_in[5];

    float4* out = (float4*)d_out;   // [8192, 1032] : out0 then out1

    dim3 grid(2 * BATCH, NCHUNK);
    ft_pipe_kernel<<<grid, THREADS>>>(idx0, val0, idx1, val1, W4, b4, out);
}

// round 12
// speedup vs baseline: 1.6336x; 1.0170x over previous
#include <cuda_runtime.h>

#define NUM_OUTPUTS 1032
#define D4 258              // 1032 floats = 258 float4 per weight row
#define CHUNK 86            // float4 per column chunk (3 chunks: 86*3 = 258)
#define NCHUNK 3
#define MAX_ACTIVE 32
#define GROUP 4             // staged loads per batch (target MLP)
#define BATCH 4096
#define THREADS 96          // 3 warps; lanes 0..85 active
#define MINBLOCKS 16        // reg cap 65536/(96*16) = 42 -> room for 4 staged float4

__global__ __launch_bounds__(THREADS, MINBLOCKS)
void ft_mlp_kernel(const int*    __restrict__ idx0,
                   const float*  __restrict__ val0,
                   const int*    __restrict__ idx1,
                   const float*  __restrict__ val1,
                   const float4* __restrict__ W4,
                   const float4* __restrict__ bias4,
                   float4*       __restrict__ out4)
{
    const int r     = blockIdx.x;          // 0..8191 : both feature sets fused
    const int chunk = blockIdx.y;          // 0..2    : slow dim -> L2 phases
    const int tid   = threadIdx.x;

    const int*   idx;
    const float* val;
    int row;
    if (r < BATCH) { idx = idx0; val = val0; row = r; }
    else           { idx = idx1; val = val1; row = r - BATCH; }

    __shared__ int   sOff[MAX_ACTIVE];     // row offsets in float4 units
    __shared__ float sVal[MAX_ACTIVE];
    if (tid < MAX_ACTIVE) {
        sOff[tid] = idx[row * MAX_ACTIVE + tid] * D4;
        sVal[tid] = val[row * MAX_ACTIVE + tid];
    }
    __syncthreads();

    if (tid >= CHUNK) return;              // no barriers below

    const int c = chunk * CHUNK + tid;     // float4 column index, 0..257
    const float4* __restrict__ Wc = W4 + c;

    float4 a = bias4[c];

    #pragma unroll
    for (int g = 0; g < MAX_ACTIVE; g += GROUP) {
        // With the 42-reg budget ptxas can now keep all GROUP loads in flight.
        float4 w[GROUP];
        #pragma unroll
        for (int j = 0; j < GROUP; ++j)
            w[j] = __ldg(Wc + sOff[g + j]);
        #pragma unroll
        for (int j = 0; j < GROUP; ++j) {
            const float v = sVal[g + j];
            a.x = fmaf(w[j].x, v, a.x);
            a.y = fmaf(w[j].y, v, a.y);
            a.z = fmaf(w[j].z, v, a.z);
            a.w = fmaf(w[j].w, v, a.w);
        }
    }

    // Streaming store: written once, never re-read.
    __stcs(out4 + (size_t)r * D4 + c, a);
}

extern "C" void kernel_launch(void* const* d_in, const int* in_sizes, int n_in,
                              void* d_out, int out_size)
{
    // metadata order:
    //   0: feature_indices_0  int32  [4096, 32]
    //   1: feature_values_0   f32    [4096, 32]
    //   2: feature_indices_1  int32  [4096, 32]
    //   3: feature_values_1   f32    [4096, 32]
    //   4: merged_weight      f32    [45056, 1032]
    //   5: bias               f32    [1032]
    const int*    idx0 = (const int*)   d_in[0];
    const float*  val0 = (const float*) d_in[1];
    const int*    idx1 = (const int*)   d_in[2];
    const float*  val1 = (const float*) d_in[3];
    const float4* W4   = (const float4*)d_in[4];
    const float4* b4   = (const float4*)d_in[5];

    float4* out = (float4*)d_out;   // [8192, 1032] : out0 then out1

    dim3 grid(2 * BATCH, NCHUNK);
    ft_mlp_kernel<<<grid, THREADS>>>(idx0, val0, idx1, val1, W4, b4, out);
}

// round 13
// speedup vs baseline: 1.8977x; 1.1617x over previous
#include <cuda_runtime.h>

#define NUM_OUTPUTS 1032
#define D4 258              // 1032 floats = 258 float4 per weight row
#define CHUNK 64            // float4 per column chunk; 4 chunks cover 256, +2 tail
#define NCHUNK 4
#define MAX_ACTIVE 32
#define BATCH 4096
#define THREADS 64          // 2 warps, all lanes active -> 32 CTAs/SM = 100% occ

__global__ __launch_bounds__(THREADS)
void ft_occ_kernel(const int*    __restrict__ idx0,
                   const float*  __restrict__ val0,
                   const int*    __restrict__ idx1,
                   const float*  __restrict__ val1,
                   const float4* __restrict__ W4,
                   const float4* __restrict__ bias4,
                   float4*       __restrict__ out4)
{
    const int r     = blockIdx.x;          // 0..8191 : both feature sets fused
    const int chunk = blockIdx.y;          // 0..3    : slow dim -> L2 phases
    const int tid   = threadIdx.x;

    const int*   idx;
    const float* val;
    int row;
    if (r < BATCH) { idx = idx0; val = val0; row = r; }
    else           { idx = idx1; val = val1; row = r - BATCH; }

    __shared__ int   sOff[MAX_ACTIVE];     // row offsets in float4 units (fits int)
    __shared__ float sVal[MAX_ACTIVE];
    if (tid < MAX_ACTIVE) {
        sOff[tid] = idx[row * MAX_ACTIVE + tid] * D4;
        sVal[tid] = val[row * MAX_ACTIVE + tid];
    }
    __syncthreads();

    const int c = chunk * CHUNK + tid;     // float4 column index, 0..255
    const float4* __restrict__ Wc = W4 + c;

    float4 a = bias4[c];

    #pragma unroll 4
    for (int k = 0; k < MAX_ACTIVE; ++k) {
        const float4 w = __ldg(Wc + sOff[k]);
        const float  v = sVal[k];
        a.x = fmaf(w.x, v, a.x);
        a.y = fmaf(w.y, v, a.y);
        a.z = fmaf(w.z, v, a.z);
        a.w = fmaf(w.w, v, a.w);
    }

    // Streaming store: written once, never re-read.
    __stcs(out4 + (size_t)r * D4 + c, a);

    // Tail columns 256, 257 (chunk 3 only): warp w reduces column 256+w.
    // Lane l contributes term k=l; butterfly-shfl sum; lane 0 stores.
    if (chunk == 3) {
        const int  w    = tid >> 5;            // warp id 0/1 -> column 256/257
        const int  lane = tid & 31;
        const int  cc   = 256 + w;
        const float4 wt = __ldg(W4 + sOff[lane] + cc);
        const float  v  = sVal[lane];
        float tx = wt.x * v, ty = wt.y * v, tz = wt.z * v, tw = wt.w * v;
        #pragma unroll
        for (int off = 16; off >= 1; off >>= 1) {
            tx += __shfl_xor_sync(0xffffffffu, tx, off);
            ty += __shfl_xor_sync(0xffffffffu, ty, off);
            tz += __shfl_xor_sync(0xffffffffu, tz, off);
            tw += __shfl_xor_sync(0xffffffffu, tw, off);
        }
        if (lane == 0) {
            const float4 b = bias4[cc];
            __stcs(out4 + (size_t)r * D4 + cc,
                   make_float4(b.x + tx, b.y + ty, b.z + tz, b.w + tw));
        }
    }
}

extern "C" void kernel_launch(void* const* d_in, const int* in_sizes, int n_in,
                              void* d_out, int out_size)
{
    // metadata order:
    //   0: feature_indices_0  int32  [4096, 32]
    //   1: feature_values_0   f32    [4096, 32]
    //   2: feature_indices_1  int32  [4096, 32]
    //   3: feature_values_1   f32    [4096, 32]
    //   4: merged_weight      f32    [45056, 1032]
    //   5: bias               f32    [1032]
    const int*    idx0 = (const int*)   d_in[0];
    const float*  val0 = (const float*) d_in[1];
    const int*    idx1 = (const int*)   d_in[2];
    const float*  val1 = (const float*) d_in[3];
    const float4* W4   = (const float4*)d_in[4];
    const float4* b4   = (const float4*)d_in[5];

    float4* out = (float4*)d_out;   // [8192, 1032] : out0 then out1

    dim3 grid(2 * BATCH, NCHUNK);
    ft_occ_kernel<<<grid, THREADS>>>(idx0, val0, idx1, val1, W4, b4, out);
}